// round 13
// baseline (speedup 1.0000x reference)
#include <cuda_runtime.h>
#include <math.h>

#define SS    2048
#define BB    8
#define EE    256
#define HHID  256
#define TT    12
#define NROWS (SS*BB)        /* 16384 */
#define CH    256            /* viterbi chunk length */
#define NC    (NROWS/CH)     /* 64 chunks */
#define NEGV  (-10000.0f)
#define STARTT 10
#define STOPT  11

// ---------------- device scratch (no allocs allowed) ----------------
__device__ float zx_buf[(size_t)2*NROWS*1024];     // x@W_ih^T + b, both dirs
__device__ float hs_buf[(size_t)2*SS*BB*HHID];     // hidden states [dir][s][b][u]
__device__ float feats_buf[(size_t)NROWS*TT];
__device__ unsigned char bptrG[(size_t)NROWS*TT];
__device__ int  Echg[NC*TT];
__device__ int  tagEndG[NC];
__device__ int  g_best;

// =============== K1: embedding gather + input projection GEMM ===============
// zx[dir][r][n] = emb[tok(r)] . w_ih_dir[n] + b_dir[n],  r = s*8+b
__global__ __launch_bounds__(256) void k_zx(const int* __restrict__ sent,
                                            const float* __restrict__ emb,
                                            const float* __restrict__ wf,
                                            const float* __restrict__ bf,
                                            const float* __restrict__ wb,
                                            const float* __restrict__ bbias)
{
    __shared__ float xs[64][33];
    __shared__ float ws[32][65];
    __shared__ int   tok[64];
    int t  = threadIdx.x;
    int m0 = blockIdx.x * 64;            // row tile (16384/64 = 256)
    int n0 = blockIdx.y * 64;            // col tile over 2048 (two dirs)
    int dir = n0 >> 10;
    int nn0 = n0 & 1023;
    const float* w    = dir ? wb    : wf;
    const float* bias = dir ? bbias : bf;

    if (t < 64) {
        int r = m0 + t;                  // r = s*8 + b
        tok[t] = sent[(r & 7) * SS + (r >> 3)];
    }
    __syncthreads();

    float acc[4][4];
    #pragma unroll
    for (int a = 0; a < 4; a++)
        #pragma unroll
        for (int q = 0; q < 4; q++) acc[a][q] = 0.f;

    int tr = t >> 4, tc = t & 15;
    for (int k0 = 0; k0 < 256; k0 += 32) {
        #pragma unroll
        for (int i = 0; i < 8; i++) {
            int idx = t * 8 + i;
            int rr = idx >> 5, kk = idx & 31;
            xs[rr][kk] = emb[(size_t)tok[rr] * 256 + k0 + kk];
            ws[kk][rr] = w[(size_t)(nn0 + rr) * 256 + k0 + kk];
        }
        __syncthreads();
        #pragma unroll
        for (int kk = 0; kk < 32; kk++) {
            float xv[4], wv[4];
            #pragma unroll
            for (int j = 0; j < 4; j++) { xv[j] = xs[tr*4+j][kk]; wv[j] = ws[kk][tc*4+j]; }
            #pragma unroll
            for (int a = 0; a < 4; a++)
                #pragma unroll
                for (int q = 0; q < 4; q++) acc[a][q] += xv[a] * wv[q];
        }
        __syncthreads();
    }
    #pragma unroll
    for (int a = 0; a < 4; a++) {
        int r = m0 + tr*4 + a;
        #pragma unroll
        for (int q = 0; q < 4; q++) {
            int c = nn0 + tc*4 + q;
            zx_buf[((size_t)dir * NROWS + r) * 1024 + c] = acc[a][q] + bias[c];
        }
    }
}

// =============== K2: LSTM recurrence, 16 chains x 8-CTA clusters ===============
__device__ __forceinline__ float sigm(float x) { return 1.f / (1.f + expf(-x)); }

__global__ void __launch_bounds__(256, 1) __cluster_dims__(8, 1, 1)
k_lstm(const float* __restrict__ whf, const float* __restrict__ whb,
       const float* __restrict__ h0,  const float* __restrict__ c0)
{
    __shared__ float hb[256];    // full h_{t-1} of this chain
    __shared__ float zb[128];    // gate pre-activations of this CTA's 32 units
    __shared__ float zxs[128];   // x-projection slice for this step
    __shared__ float cst[32];    // persistent cell-state slice

    int t    = threadIdx.x;
    int cid  = blockIdx.x >> 3;  // chain 0..15
    int rank = blockIdx.x & 7;   // slice in cluster
    int d = cid >> 3, b = cid & 7;
    const float* wh = d ? whb : whf;

    // local row l = gate*32 + uu -> global row gate*256 + rank*32 + uu
    int l    = t >> 1;
    int grow = ((l >> 5) << 8) + rank * 32 + (l & 31);
    int half = (t & 1) * 128;

    float w[128];
    #pragma unroll
    for (int j = 0; j < 128; j++) w[j] = wh[(size_t)grow * 256 + half + j];
    if (t < 32) cst[t] = c0[(d * 8 + b) * 256 + rank * 32 + t];

    for (int step = 0; step < SS; step++) {
        int s = d ? (SS - 1 - step) : step;
        const float* hp;
        if (step == 0) hp = h0 + (d * 8 + b) * 256;
        else { int ps = d ? s + 1 : s - 1;
               hp = hs_buf + ((size_t)(d * SS + ps) * 8 + b) * 256; }
        hb[t] = __ldcg(hp + t);
        if (t < 128)
            zxs[t] = zx_buf[((size_t)d * NROWS + s * 8 + b) * 1024
                            + ((t >> 5) << 8) + rank * 32 + (t & 31)];
        __syncthreads();

        float a0 = 0.f, a1 = 0.f, a2 = 0.f, a3 = 0.f;
        #pragma unroll
        for (int j = 0; j < 128; j += 4) {
            a0 += w[j]   * hb[half + j];
            a1 += w[j+1] * hb[half + j + 1];
            a2 += w[j+2] * hb[half + j + 2];
            a3 += w[j+3] * hb[half + j + 3];
        }
        float acc = (a0 + a1) + (a2 + a3);
        acc += __shfl_xor_sync(0xffffffffu, acc, 1);
        if ((t & 1) == 0) zb[l] = acc + zxs[l];
        __syncthreads();

        if (t < 32) {
            float zi = zb[t], zf = zb[32 + t], zg = zb[64 + t], zo = zb[96 + t];
            float c = sigm(zf) * cst[t] + sigm(zi) * tanhf(zg);
            cst[t] = c;
            float h = sigm(zo) * tanhf(c);
            __stcg(&hs_buf[((size_t)(d * SS + s) * 8 + b) * 256 + rank * 32 + t], h);
        }
        // cluster barrier: release/acquire orders the global h stores
        asm volatile("barrier.cluster.arrive.aligned;" ::: "memory");
        asm volatile("barrier.cluster.wait.aligned;"   ::: "memory");
    }
}

// =============== K3: feats = concat(hf,hb) @ W_out^T + b_out ===============
__global__ __launch_bounds__(256) void k_feats(const float* __restrict__ Wout,
                                               const float* __restrict__ bout)
{
    __shared__ float wsm[12 * 512];
    int t = threadIdx.x, lane = t & 31, w = t >> 5;
    for (int i = t; i < 12 * 512; i += 256) wsm[i] = Wout[i];
    __syncthreads();

    int row = blockIdx.x * 8 + w;          // row = b*S + s   (2048 blocks)
    int b = row >> 11, s = row & 2047;
    const float* hf = hs_buf + ((size_t)(0 * SS + s) * 8 + b) * 256;
    const float* hr = hs_buf + ((size_t)(1 * SS + s) * 8 + b) * 256;

    int base = lane * 16;                  // lane's slice of concat[512]
    float x[16];
    #pragma unroll
    for (int j = 0; j < 16; j++) {
        int k = base + j;
        x[j] = (k < 256) ? hf[k] : hr[k - 256];
    }
    float acc[12];
    #pragma unroll
    for (int tg = 0; tg < 12; tg++) acc[tg] = 0.f;
    #pragma unroll
    for (int j = 0; j < 16; j++) {
        float xv = x[j];
        #pragma unroll
        for (int tg = 0; tg < 12; tg++) acc[tg] += xv * wsm[tg * 512 + base + j];
    }
    #pragma unroll
    for (int tg = 0; tg < 12; tg++) {
        float v = acc[tg];
        #pragma unroll
        for (int o = 16; o; o >>= 1) v += __shfl_xor_sync(0xffffffffu, v, o);
        if (lane == 0) feats_buf[(size_t)row * 12 + tg] = v + bout[tg];
    }
}

// =============== K4a: exact f32 sequential Viterbi forward scan ===============
__global__ __launch_bounds__(256) void k_vfwd(const float* __restrict__ tr,
                                              float* __restrict__ outp)
{
    __shared__ float sb[2][CH * 12];
    int t = threadIdx.x, w = t >> 5, lane = t & 31;

    float trow[12];
    #pragma unroll
    for (int p = 0; p < 12; p++) trow[p] = (lane < 12) ? tr[lane * 12 + p] : 0.f;

    for (int i = t; i < CH * 12; i += 256) sb[0][i] = feats_buf[i];
    __syncthreads();

    float fv = (lane == STARTT) ? 0.f : NEGV;   // init_v

    for (int k = 0; k < NC; k++) {
        int buf = k & 1;
        if (w == 0) {
            for (int tt = 0; tt < CH; tt++) {
                float feat = (lane < 12) ? sb[buf][tt * 12 + lane] : 0.f;
                float v[12];
                #pragma unroll
                for (int p = 0; p < 12; p++)
                    v[p] = __shfl_sync(0xffffffffu, fv, p) + trow[p];
                // exact max via fmax tree (max is exact; association-free)
                float m0 = fmaxf(v[0], v[1]),  m1 = fmaxf(v[2], v[3]);
                float m2 = fmaxf(v[4], v[5]),  m3 = fmaxf(v[6], v[7]);
                float m4 = fmaxf(v[8], v[9]),  m5 = fmaxf(v[10], v[11]);
                float n0 = fmaxf(m0, m1), n1 = fmaxf(m2, m3), n2 = fmaxf(m4, m5);
                float mx = fmaxf(fmaxf(n0, n1), n2);
                // first-index argmax (off critical path)
                int arg = 11;
                #pragma unroll
                for (int p = 10; p >= 0; p--) arg = (v[p] == mx) ? p : arg;
                if (lane < 12)
                    bptrG[(size_t)(k * CH + tt) * 12 + lane] = (unsigned char)arg;
                fv = mx + feat;
            }
        } else if (k + 1 < NC) {
            for (int i = t - 32; i < CH * 12; i += 224)
                sb[buf ^ 1][i] = feats_buf[(size_t)(k + 1) * CH * 12 + i];
        }
        __syncthreads();
    }

    if (w == 0) {
        float term = (lane < 12) ? fv + tr[STOPT * 12 + lane] : -3.0e38f;
        float bv = -3.0e38f; int bi = 0;
        #pragma unroll
        for (int p = 0; p < 12; p++) {
            float tv = __shfl_sync(0xffffffffu, term, p);
            if (tv > bv) { bv = tv; bi = p; }
        }
        if (lane == 0) { g_best = bi; outp[0] = bv; }
    }
}

// =============== K4b: chunk exit-tag tables (parallel) ===============
__global__ __launch_bounds__(256) void k_bt1()
{
    __shared__ unsigned char bp[CH * 12];
    int c = blockIdx.x, t = threadIdx.x;
    for (int i = t; i < CH * 12; i += 256) bp[i] = bptrG[(size_t)c * CH * 12 + i];
    __syncthreads();
    if (t < 12) {
        int tag = t;
        for (int tt = CH - 1; tt >= 1; tt--) tag = bp[tt * 12 + tag];
        Echg[c * 12 + t] = bp[tag];   // tag at previous chunk's last step
    }
}

// =============== K4c: chain chunk end-tags (tiny sequential) ===============
__global__ void k_bt2()
{
    if (threadIdx.x == 0 && blockIdx.x == 0) {
        int tag = g_best;
        for (int c = NC - 1; c >= 0; c--) { tagEndG[c] = tag; tag = Echg[c * 12 + tag]; }
    }
}

// =============== K4d: emit best path (parallel per chunk) ===============
__global__ __launch_bounds__(256) void k_bt3(float* __restrict__ outp)
{
    __shared__ unsigned char bp[CH * 12];
    __shared__ int pl[CH];
    int c = blockIdx.x, t = threadIdx.x;
    for (int i = t; i < CH * 12; i += 256) bp[i] = bptrG[(size_t)c * CH * 12 + i];
    __syncthreads();
    if (t == 0) {
        int tag = tagEndG[c];
        pl[CH - 1] = tag;
        for (int tt = CH - 1; tt >= 1; tt--) { tag = bp[tt * 12 + tag]; pl[tt - 1] = tag; }
    }
    __syncthreads();
    for (int i = t; i < CH; i += 256) outp[1 + c * CH + i] = (float)pl[i];
}

// ======================= launcher =======================
extern "C" void kernel_launch(void* const* d_in, const int* in_sizes, int n_in,
                              void* d_out, int out_size)
{
    const int*   sent  = (const int*)  d_in[0];
    const float* emb   = (const float*)d_in[1];
    const float* wihf  = (const float*)d_in[2];
    const float* whhf  = (const float*)d_in[3];
    const float* bf    = (const float*)d_in[4];
    const float* wihb  = (const float*)d_in[5];
    const float* whhb  = (const float*)d_in[6];
    const float* bb    = (const float*)d_in[7];
    const float* h0    = (const float*)d_in[8];
    const float* c0    = (const float*)d_in[9];
    const float* Wout  = (const float*)d_in[10];
    const float* bout  = (const float*)d_in[11];
    const float* trans = (const float*)d_in[12];
    float* outp = (float*)d_out;

    dim3 gzx(NROWS / 64, 2048 / 64);
    k_zx<<<gzx, 256>>>(sent, emb, wihf, bf, wihb, bb);
    k_lstm<<<128, 256>>>(whhf, whhb, h0, c0);
    k_feats<<<NROWS / 8, 256>>>(Wout, bout);
    k_vfwd<<<1, 256>>>(trans, outp);
    k_bt1<<<NC, 256>>>();
    k_bt2<<<1, 32>>>();
    k_bt3<<<NC, 256>>>(outp);
}

// round 14
// speedup vs baseline: 1.5949x; 1.5949x over previous
#include <cuda_runtime.h>
#include <math.h>

#define SS    2048
#define BB    8
#define EE    256
#define HHID  256
#define TT    12
#define NROWS (SS*BB)        /* 16384 */
#define CH    256            /* viterbi chunk length */
#define NC    (NROWS/CH)     /* 64 chunks */
#define NEGV  (-10000.0f)
#define STARTT 10
#define STOPT  11

// ---------------- device scratch (no allocs allowed) ----------------
__device__ float zx_buf[(size_t)2*NROWS*1024];     // x@W_ih^T + b, both dirs
__device__ float hs_buf[(size_t)2*SS*BB*HHID];     // hidden states [dir][s][b][u]
__device__ float feats_buf[(size_t)NROWS*TT];
__device__ unsigned char bptrG[(size_t)NROWS*TT];
__device__ int  Echg[NC*TT];
__device__ int  tagEndG[NC];
__device__ int  g_best;

__device__ __forceinline__ unsigned smem_u32(const void* p){
    unsigned a;
    asm("{ .reg .u64 t; cvta.to.shared.u64 t, %1; cvt.u32.u64 %0, t; }" : "=r"(a) : "l"(p));
    return a;
}
__device__ __forceinline__ void fma2(unsigned long long& d, unsigned long long a, unsigned long long b){
    asm("fma.rn.f32x2 %0, %1, %2, %0;" : "+l"(d) : "l"(a), "l"(b));
}
__device__ __forceinline__ float sigm(float x) { return 1.f / (1.f + expf(-x)); }

// =============== K1: embedding gather + input projection GEMM ===============
__global__ __launch_bounds__(256) void k_zx(const int* __restrict__ sent,
                                            const float* __restrict__ emb,
                                            const float* __restrict__ wf,
                                            const float* __restrict__ bf,
                                            const float* __restrict__ wb,
                                            const float* __restrict__ bbias)
{
    __shared__ float xs[64][33];
    __shared__ float ws[32][65];
    __shared__ int   tok[64];
    int t  = threadIdx.x;
    int m0 = blockIdx.x * 64;
    int n0 = blockIdx.y * 64;
    int dir = n0 >> 10;
    int nn0 = n0 & 1023;
    const float* w    = dir ? wb    : wf;
    const float* bias = dir ? bbias : bf;

    if (t < 64) {
        int r = m0 + t;                  // r = s*8 + b
        tok[t] = sent[(r & 7) * SS + (r >> 3)];
    }
    __syncthreads();

    float acc[4][4];
    #pragma unroll
    for (int a = 0; a < 4; a++)
        #pragma unroll
        for (int q = 0; q < 4; q++) acc[a][q] = 0.f;

    int tr = t >> 4, tc = t & 15;
    for (int k0 = 0; k0 < 256; k0 += 32) {
        #pragma unroll
        for (int i = 0; i < 8; i++) {
            int idx = t * 8 + i;
            int rr = idx >> 5, kk = idx & 31;
            xs[rr][kk] = emb[(size_t)tok[rr] * 256 + k0 + kk];
            ws[kk][rr] = w[(size_t)(nn0 + rr) * 256 + k0 + kk];
        }
        __syncthreads();
        #pragma unroll
        for (int kk = 0; kk < 32; kk++) {
            float xv[4], wv[4];
            #pragma unroll
            for (int j = 0; j < 4; j++) { xv[j] = xs[tr*4+j][kk]; wv[j] = ws[kk][tc*4+j]; }
            #pragma unroll
            for (int a = 0; a < 4; a++)
                #pragma unroll
                for (int q = 0; q < 4; q++) acc[a][q] += xv[a] * wv[q];
        }
        __syncthreads();
    }
    #pragma unroll
    for (int a = 0; a < 4; a++) {
        int r = m0 + tr*4 + a;
        #pragma unroll
        for (int q = 0; q < 4; q++) {
            int c = nn0 + tc*4 + q;
            zx_buf[((size_t)dir * NROWS + r) * 1024 + c] = acc[a][q] + bias[c];
        }
    }
}

// =============== K2: LSTM recurrence — 8-CTA clusters, DSMEM h-exchange ===============
__global__ void __launch_bounds__(256, 1) __cluster_dims__(8, 1, 1)
k_lstm(const float* __restrict__ whf, const float* __restrict__ whb,
       const float* __restrict__ h0,  const float* __restrict__ c0)
{
    __shared__ float hbuf[2][256];       // double-buffered full h of this chain
    __shared__ float zb[128];            // gate pre-activations (this CTA's 32 units)
    __shared__ float cst[32];            // persistent cell-state slice
    __shared__ __align__(8) unsigned long long mbar;

    int t    = threadIdx.x;
    int cid  = blockIdx.x >> 3;          // chain 0..15
    int rank = blockIdx.x & 7;           // rank within cluster
    int d = cid >> 3, b = cid & 7;
    const float* wh = d ? whb : whf;

    unsigned mlocal = smem_u32(&mbar);
    if (t == 0)
        asm volatile("mbarrier.init.shared.b64 [%0], %1;" :: "r"(mlocal), "r"(8) : "memory");

    // weight slice: local row l = gate*32+uu -> global row gate*256 + rank*32 + uu
    int l    = t >> 1;
    int half = (t & 1) * 128;
    int grow = ((l >> 5) << 8) + rank * 32 + (l & 31);
    unsigned long long w2[64];
    {
        const unsigned long long* wr = (const unsigned long long*)(wh + (size_t)grow * 256 + half);
        #pragma unroll
        for (int j = 0; j < 64; j++) w2[j] = wr[j];
    }
    hbuf[0][t] = h0[(d * 8 + b) * 256 + t];
    if (t < 32) cst[t] = c0[(d * 8 + b) * 256 + rank * 32 + t];

    // precompute remote SMEM addresses (this CTA's h slice in each peer's hbuf[0])
    unsigned rbar = 0;
    if (t < 8)
        asm("mapa.shared::cluster.u32 %0, %1, %2;" : "=r"(rbar) : "r"(mlocal), "r"(t));
    unsigned hsl = smem_u32(&hbuf[0][rank * 32 + (t & 31)]);
    unsigned ra[8];
    #pragma unroll
    for (int r = 0; r < 8; r++)
        asm("mapa.shared::cluster.u32 %0, %1, %2;" : "=r"(ra[r]) : "r"(hsl), "r"(r));

    __syncthreads();
    // publish mbarrier inits cluster-wide (once)
    asm volatile("barrier.cluster.arrive.aligned;" ::: "memory");
    asm volatile("barrier.cluster.wait.aligned;"   ::: "memory");

    size_t zxd = (size_t)d * NROWS * 1024;
    for (int si = 0; si < SS; si++) {
        int s = d ? (SS - 1 - si) : si;
        // prefetch this step's zx element before the barrier wait (hides DRAM latency)
        float zxv = 0.f;
        if ((t & 1) == 0)
            zxv = __ldcg(&zx_buf[zxd + (size_t)(s * 8 + b) * 1024
                                 + ((l >> 5) << 8) + rank * 32 + (l & 31)]);

        if (si > 0) {
            unsigned par = (si - 1) & 1, done = 0;
            while (!done)
                asm volatile("{ .reg .pred p; mbarrier.try_wait.parity.acquire.cluster.shared::cta.b64 p, [%1], %2, 0x989680; selp.b32 %0,1,0,p; }"
                             : "=r"(done) : "r"(mlocal), "r"(par) : "memory");
        }
        int rb = si & 1;

        const unsigned long long* h2 = (const unsigned long long*)(&hbuf[rb][half]);
        unsigned long long a0 = 0ull, a1 = 0ull, a2 = 0ull, a3 = 0ull;
        #pragma unroll
        for (int j = 0; j < 64; j += 4) {
            fma2(a0, w2[j],   h2[j]);
            fma2(a1, w2[j+1], h2[j+1]);
            fma2(a2, w2[j+2], h2[j+2]);
            fma2(a3, w2[j+3], h2[j+3]);
        }
        float s0,s1,s2,s3,s4,s5,s6,s7;
        asm("mov.b64 {%0,%1}, %2;" : "=f"(s0), "=f"(s1) : "l"(a0));
        asm("mov.b64 {%0,%1}, %2;" : "=f"(s2), "=f"(s3) : "l"(a1));
        asm("mov.b64 {%0,%1}, %2;" : "=f"(s4), "=f"(s5) : "l"(a2));
        asm("mov.b64 {%0,%1}, %2;" : "=f"(s6), "=f"(s7) : "l"(a3));
        float acc = ((s0 + s1) + (s2 + s3)) + ((s4 + s5) + (s6 + s7));
        acc += __shfl_xor_sync(0xffffffffu, acc, 1);
        if ((t & 1) == 0) zb[l] = acc + zxv;
        __syncthreads();

        if (t < 32) {
            float zi = zb[t], zf = zb[32 + t], zg = zb[64 + t], zo = zb[96 + t];
            float c = sigm(zf) * cst[t] + sigm(zi) * tanhf(zg);
            cst[t] = c;
            float h = sigm(zo) * tanhf(c);
            __stcg(&hs_buf[((size_t)(d * SS + s) * 8 + b) * 256 + rank * 32 + t], h);
            unsigned wofs = (unsigned)((rb ^ 1) << 10);   // hbuf[0] -> hbuf[1] byte offset
            unsigned hu = __float_as_uint(h);
            #pragma unroll
            for (int r = 0; r < 8; r++)
                asm volatile("st.shared::cluster.u32 [%0], %1;" :: "r"(ra[r] + wofs), "r"(hu) : "memory");
            asm volatile("fence.acq_rel.cluster;" ::: "memory");
        }
        __syncthreads();
        if (t < 8)
            asm volatile("mbarrier.arrive.release.cluster.shared::cluster.b64 _, [%0];" :: "r"(rbar) : "memory");
    }
    // drain final phase so no CTA exits while peers still target its SMEM
    {
        unsigned done = 0;
        while (!done)
            asm volatile("{ .reg .pred p; mbarrier.try_wait.parity.acquire.cluster.shared::cta.b64 p, [%1], %2, 0x989680; selp.b32 %0,1,0,p; }"
                         : "=r"(done) : "r"(mlocal), "r"((unsigned)((SS - 1) & 1)) : "memory");
    }
}

// =============== K3: feats = concat(hf,hb) @ W_out^T + b_out ===============
__global__ __launch_bounds__(256) void k_feats(const float* __restrict__ Wout,
                                               const float* __restrict__ bout)
{
    __shared__ float wsm[12 * 512];
    int t = threadIdx.x, lane = t & 31, w = t >> 5;
    for (int i = t; i < 12 * 512; i += 256) wsm[i] = Wout[i];
    __syncthreads();

    int row = blockIdx.x * 8 + w;
    int b = row >> 11, s = row & 2047;
    const float* hf = hs_buf + ((size_t)(0 * SS + s) * 8 + b) * 256;
    const float* hr = hs_buf + ((size_t)(1 * SS + s) * 8 + b) * 256;

    int base = lane * 16;
    float x[16];
    #pragma unroll
    for (int j = 0; j < 16; j++) {
        int k = base + j;
        x[j] = (k < 256) ? hf[k] : hr[k - 256];
    }
    float acc[12];
    #pragma unroll
    for (int tg = 0; tg < 12; tg++) acc[tg] = 0.f;
    #pragma unroll
    for (int j = 0; j < 16; j++) {
        float xv = x[j];
        #pragma unroll
        for (int tg = 0; tg < 12; tg++) acc[tg] += xv * wsm[tg * 512 + base + j];
    }
    #pragma unroll
    for (int tg = 0; tg < 12; tg++) {
        float v = acc[tg];
        #pragma unroll
        for (int o = 16; o; o >>= 1) v += __shfl_xor_sync(0xffffffffu, v, o);
        if (lane == 0) feats_buf[(size_t)row * 12 + tg] = v + bout[tg];
    }
}

// =============== K4a: exact f32 sequential Viterbi forward scan ===============
__global__ __launch_bounds__(256) void k_vfwd(const float* __restrict__ tr,
                                              float* __restrict__ outp)
{
    __shared__ float sb[2][CH * 12];
    int t = threadIdx.x, w = t >> 5, lane = t & 31;

    float trow[12];
    #pragma unroll
    for (int p = 0; p < 12; p++) trow[p] = (lane < 12) ? tr[lane * 12 + p] : 0.f;

    for (int i = t; i < CH * 12; i += 256) sb[0][i] = feats_buf[i];
    __syncthreads();

    float fv = (lane == STARTT) ? 0.f : NEGV;

    for (int k = 0; k < NC; k++) {
        int buf = k & 1;
        if (w == 0) {
            for (int tt = 0; tt < CH; tt++) {
                float feat = (lane < 12) ? sb[buf][tt * 12 + lane] : 0.f;
                float v[12];
                #pragma unroll
                for (int p = 0; p < 12; p++)
                    v[p] = __shfl_sync(0xffffffffu, fv, p) + trow[p];
                float m0 = fmaxf(v[0], v[1]),  m1 = fmaxf(v[2], v[3]);
                float m2 = fmaxf(v[4], v[5]),  m3 = fmaxf(v[6], v[7]);
                float m4 = fmaxf(v[8], v[9]),  m5 = fmaxf(v[10], v[11]);
                float n0 = fmaxf(m0, m1), n1 = fmaxf(m2, m3), n2 = fmaxf(m4, m5);
                float mx = fmaxf(fmaxf(n0, n1), n2);
                int arg = 11;
                #pragma unroll
                for (int p = 10; p >= 0; p--) arg = (v[p] == mx) ? p : arg;
                if (lane < 12)
                    bptrG[(size_t)(k * CH + tt) * 12 + lane] = (unsigned char)arg;
                fv = mx + feat;
            }
        } else if (k + 1 < NC) {
            for (int i = t - 32; i < CH * 12; i += 224)
                sb[buf ^ 1][i] = feats_buf[(size_t)(k + 1) * CH * 12 + i];
        }
        __syncthreads();
    }

    if (w == 0) {
        float term = (lane < 12) ? fv + tr[STOPT * 12 + lane] : -3.0e38f;
        float bv = -3.0e38f; int bi = 0;
        #pragma unroll
        for (int p = 0; p < 12; p++) {
            float tv = __shfl_sync(0xffffffffu, term, p);
            if (tv > bv) { bv = tv; bi = p; }
        }
        if (lane == 0) { g_best = bi; outp[0] = bv; }
    }
}

// =============== K4b: chunk exit-tag tables (parallel) ===============
__global__ __launch_bounds__(256) void k_bt1()
{
    __shared__ unsigned char bp[CH * 12];
    int c = blockIdx.x, t = threadIdx.x;
    for (int i = t; i < CH * 12; i += 256) bp[i] = bptrG[(size_t)c * CH * 12 + i];
    __syncthreads();
    if (t < 12) {
        int tag = t;
        for (int tt = CH - 1; tt >= 1; tt--) tag = bp[tt * 12 + tag];
        Echg[c * 12 + t] = bp[tag];
    }
}

// =============== K4c: chain chunk end-tags (tiny sequential) ===============
__global__ void k_bt2()
{
    if (threadIdx.x == 0 && blockIdx.x == 0) {
        int tag = g_best;
        for (int c = NC - 1; c >= 0; c--) { tagEndG[c] = tag; tag = Echg[c * 12 + tag]; }
    }
}

// =============== K4d: emit best path (parallel per chunk) ===============
__global__ __launch_bounds__(256) void k_bt3(float* __restrict__ outp)
{
    __shared__ unsigned char bp[CH * 12];
    __shared__ int pl[CH];
    int c = blockIdx.x, t = threadIdx.x;
    for (int i = t; i < CH * 12; i += 256) bp[i] = bptrG[(size_t)c * CH * 12 + i];
    __syncthreads();
    if (t == 0) {
        int tag = tagEndG[c];
        pl[CH - 1] = tag;
        for (int tt = CH - 1; tt >= 1; tt--) { tag = bp[tt * 12 + tag]; pl[tt - 1] = tag; }
    }
    __syncthreads();
    for (int i = t; i < CH; i += 256) outp[1 + c * CH + i] = (float)pl[i];
}

// ======================= launcher =======================
extern "C" void kernel_launch(void* const* d_in, const int* in_sizes, int n_in,
                              void* d_out, int out_size)
{
    const int*   sent  = (const int*)  d_in[0];
    const float* emb   = (const float*)d_in[1];
    const float* wihf  = (const float*)d_in[2];
    const float* whhf  = (const float*)d_in[3];
    const float* bf    = (const float*)d_in[4];
    const float* wihb  = (const float*)d_in[5];
    const float* whhb  = (const float*)d_in[6];
    const float* bb    = (const float*)d_in[7];
    const float* h0    = (const float*)d_in[8];
    const float* c0    = (const float*)d_in[9];
    const float* Wout  = (const float*)d_in[10];
    const float* bout  = (const float*)d_in[11];
    const float* trans = (const float*)d_in[12];
    float* outp = (float*)d_out;

    dim3 gzx(NROWS / 64, 2048 / 64);
    k_zx<<<gzx, 256>>>(sent, emb, wihf, bf, wihb, bb);
    k_lstm<<<128, 256>>>(whhf, whhb, h0, c0);
    k_feats<<<NROWS / 8, 256>>>(Wout, bout);
    k_vfwd<<<1, 256>>>(trans, outp);
    k_bt1<<<NC, 256>>>();
    k_bt2<<<1, 32>>>();
    k_bt3<<<NC, 256>>>(outp);
}